// round 4
// baseline (speedup 1.0000x reference)
#include <cuda_runtime.h>
#include <math.h>

#define BB   2048
#define NN   256
#define MM   64
#define UU   512
#define INW  10
#define KBIG 592    // 10 + 64 + 512, padded to multiple of 16
#define RWC  272    // 70 + 198, padded to multiple of 16
#define HRW  576    // 512 + 64
#define CLIPV 20.0f

// ---------------- scratch (static __device__, no allocation) ----------------
__device__ float g_Abig[(size_t)BB * KBIG];     // [x | R0 | H0 | 0pad]
__device__ float g_Wbig[(size_t)KBIG * 2048];   // [Wx[:10]; Wprep@Wx[10:]; Wh; 0pad]
__device__ float g_bbig[2048];                  // bl + bprep@Wx[10:]
__device__ float g_z[(size_t)BB * 2048];        // LSTM preactivations
__device__ float g_Ahr[(size_t)BB * HRW];       // [h | R_t]
__device__ float g_Wcomb[(size_t)UU * RWC];     // [Wr | Ww | 0pad]
__device__ float g_bcomb[RWC];
__device__ float g_rw[(size_t)BB * RWC];        // [r_out | w_out]

// output offsets (floats)
#define OUT_Y  0
#define OUT_MT ((size_t)BB * UU)
#define OUT_RT (OUT_MT + (size_t)BB * NN * MM)
#define OUT_WR (OUT_RT + (size_t)BB * MM)
#define OUT_WW (OUT_WR + (size_t)BB * NN)

// ---------------- helpers ----------------
__device__ __forceinline__ float sigmf(float x) { return 1.f / (1.f + expf(-x)); }
__device__ __forceinline__ float softplusf(float x) { return x > 20.f ? x : log1pf(expf(x)); }

__device__ __forceinline__ float blockSum256(float v, float* red) {
#pragma unroll
    for (int o = 16; o; o >>= 1) v += __shfl_xor_sync(0xffffffffu, v, o);
    if ((threadIdx.x & 31) == 0) red[threadIdx.x >> 5] = v;
    __syncthreads();
    float t = 0.f;
#pragma unroll
    for (int i = 0; i < 8; i++) t += red[i];
    __syncthreads();
    return t;
}

__device__ __forceinline__ float blockMax256(float v, float* red) {
#pragma unroll
    for (int o = 16; o; o >>= 1) v = fmaxf(v, __shfl_xor_sync(0xffffffffu, v, o));
    if ((threadIdx.x & 31) == 0) red[threadIdx.x >> 5] = v;
    __syncthreads();
    float t = -1e30f;
#pragma unroll
    for (int i = 0; i < 8; i++) t = fmaxf(t, red[i]);
    __syncthreads();
    return t;
}

// ---------------- double-buffered tiled fp32 GEMM: C = A@B + bias ----------
// A: [Mrows x K] row-major (lda), B: [K x Ncols] row-major (ldb).
// Requires: Mrows % MT == 0, K % KT == 0, lda/ldb/ldc % 4 == 0.
template <int MT, int NT, int KT, int TM, int TN, bool DOCLIP>
__global__ void __launch_bounds__(256) sgemm_kernel(
    const float* __restrict__ A, int lda,
    const float* __restrict__ B, int ldb,
    const float* __restrict__ bias,
    float* __restrict__ C, int ldc,
    int Ncols, int K)
{
    static_assert(MT * (KT / 4) == 256, "A load mapping");
    static_assert(KT * (NT / 4) == 256, "B load mapping");
    static_assert((MT / TM) * (NT / TN) == 256, "thread tiling");

    const int tid = threadIdx.x;
    const int tx = tid % (NT / TN);
    const int ty = tid / (NT / TN);
    const int m0 = blockIdx.y * MT;
    const int n0 = blockIdx.x * NT;

    __shared__ float As[2][KT][MT];
    __shared__ float Bs[2][KT][NT];

    float acc[TM][TN];
#pragma unroll
    for (int i = 0; i < TM; i++)
#pragma unroll
        for (int j = 0; j < TN; j++) acc[i][j] = 0.f;

    const int arow = tid / (KT / 4);
    const int ac   = (tid % (KT / 4)) * 4;
    const int brow = tid / (NT / 4);
    const int bc   = (tid % (NT / 4)) * 4;
    const bool bok = (n0 + bc) < Ncols;
    const float4 f4z = make_float4(0.f, 0.f, 0.f, 0.f);

    // preload tile 0 into buffer 0
    {
        float4 va = *(const float4*)&A[(size_t)(m0 + arow) * lda + ac];
        float4 vb = bok ? *(const float4*)&B[(size_t)brow * ldb + n0 + bc] : f4z;
        As[0][ac + 0][arow] = va.x;
        As[0][ac + 1][arow] = va.y;
        As[0][ac + 2][arow] = va.z;
        As[0][ac + 3][arow] = va.w;
        *(float4*)&Bs[0][brow][bc] = vb;
    }
    __syncthreads();

    int buf = 0;
    for (int k0 = 0; k0 < K; k0 += KT) {
        const bool has_next = (k0 + KT) < K;
        float4 na = f4z, nb = f4z;
        if (has_next) {
            na = *(const float4*)&A[(size_t)(m0 + arow) * lda + k0 + KT + ac];
            nb = bok ? *(const float4*)&B[(size_t)(k0 + KT + brow) * ldb + n0 + bc] : f4z;
        }
#pragma unroll
        for (int k = 0; k < KT; k++) {
            float a[TM], b[TN];
#pragma unroll
            for (int i = 0; i < TM; i++) a[i] = As[buf][k][ty * TM + i];
#pragma unroll
            for (int j = 0; j < TN; j++) b[j] = Bs[buf][k][tx * TN + j];
#pragma unroll
            for (int i = 0; i < TM; i++)
#pragma unroll
                for (int j = 0; j < TN; j++) acc[i][j] = fmaf(a[i], b[j], acc[i][j]);
        }
        if (has_next) {
            const int nbuf = buf ^ 1;
            As[nbuf][ac + 0][arow] = na.x;
            As[nbuf][ac + 1][arow] = na.y;
            As[nbuf][ac + 2][arow] = na.z;
            As[nbuf][ac + 3][arow] = na.w;
            *(float4*)&Bs[nbuf][brow][bc] = nb;
            __syncthreads();
        }
        buf ^= 1;
    }

#pragma unroll
    for (int i = 0; i < TM; i++) {
        int r = m0 + ty * TM + i;
#pragma unroll
        for (int j = 0; j < TN; j++) {
            int c = n0 + tx * TN + j;
            if (c < Ncols) {
                float v = acc[i][j] + (bias ? bias[c] : 0.f);
                if (DOCLIP) v = fminf(CLIPV, fmaxf(-CLIPV, v));
                C[(size_t)r * ldc + c] = v;
            }
        }
    }
}

// ---------------- packing kernels ----------------
__global__ void packA_kernel(const float* __restrict__ x,
                             const float* __restrict__ R0,
                             const float* __restrict__ H0)
{
    int c = blockIdx.x * 128 + threadIdx.x;
    int b = blockIdx.y;
    if (c >= KBIG) return;
    float v = 0.f;
    if (c < INW)               v = x[b * INW + c];
    else if (c < INW + MM)     v = R0[b * MM + (c - INW)];
    else if (c < INW + MM + UU) v = H0[b * UU + (c - (INW + MM))];
    g_Abig[(size_t)b * KBIG + c] = v;
}

__global__ void packWbig_kernel(const float* __restrict__ Wx,
                                const float* __restrict__ Wh)
{
    int c = blockIdx.x * 256 + threadIdx.x;
    int r = blockIdx.y;
    if (r >= 10 && r < 74) return;  // filled by fuse GEMM
    float v = 0.f;
    if (r < 10)       v = Wx[(size_t)r * 2048 + c];
    else if (r < 586) v = Wh[(size_t)(r - 74) * 2048 + c];
    g_Wbig[(size_t)r * 2048 + c] = v;
}

__global__ void bbig_kernel(const float* __restrict__ bl,
                            const float* __restrict__ bprep,
                            const float* __restrict__ Wx)
{
    int c = blockIdx.x * 256 + threadIdx.x;
    float acc = bl[c];
    for (int u = 0; u < UU; u++)
        acc = fmaf(bprep[u], Wx[(size_t)(10 + u) * 2048 + c], acc);
    g_bbig[c] = acc;
}

__global__ void packWcomb_kernel(const float* __restrict__ Wr,
                                 const float* __restrict__ Ww)
{
    int c = threadIdx.x;   // 272 threads
    int u = blockIdx.x;    // 512 blocks
    float v = 0.f;
    if (c < 70)       v = Wr[u * 70 + c];
    else if (c < 268) v = Ww[u * 198 + (c - 70)];
    g_Wcomb[u * RWC + c] = v;
}

__global__ void bcomb_kernel(const float* __restrict__ br,
                             const float* __restrict__ bw)
{
    int c = threadIdx.x;
    float v = 0.f;
    if (c < 70)       v = br[c];
    else if (c < 268) v = bw[c - 70];
    g_bcomb[c] = v;
}

// ---------------- LSTM elementwise ----------------
__global__ void lstm_kernel(const float* __restrict__ C0)
{
    int t = blockIdx.x * blockDim.x + threadIdx.x;
    if (t >= BB * UU) return;
    int b = t >> 9;
    int u = t & 511;
    const float* zr = g_z + (size_t)b * 2048;
    float iv = zr[u], fv = zr[512 + u], gv = zr[1024 + u], ov = zr[1536 + u];
    float ct = sigmf(fv) * C0[t] + sigmf(iv) * tanhf(gv);
    float h = sigmf(ov) * tanhf(ct);
    h = fminf(CLIPV, fmaxf(-CLIPV, h));
    g_Ahr[(size_t)b * HRW + u] = h;
}

// ---------------- fused addressing + memory update ----------------
// one block per batch row, 256 threads (one per memory slot n)
__global__ void __launch_bounds__(256) addr_kernel(
    const float* __restrict__ m0,
    const float* __restrict__ A0,
    float* __restrict__ out)
{
    const int b = blockIdx.x;
    const int n = threadIdx.x;
    const float* rwp = g_rw + (size_t)b * RWC;

    __shared__ float kr[MM], kw[MM], dels[MM], adds[MM];
    __shared__ float wgs[NN], wrs[NN];
    __shared__ float red[8];

    if (n < MM) {
        kr[n]   = tanhf(rwp[n]);
        kw[n]   = tanhf(rwp[70 + n]);
        dels[n] = sigmf(rwp[140 + n]);
        adds[n] = tanhf(rwp[204 + n]);
    }
    __syncthreads();

    // this thread's memory row
    float row[MM];
    const float4* mp = (const float4*)(m0 + ((size_t)b * NN + n) * MM);
#pragma unroll
    for (int i = 0; i < MM / 4; i++) {
        float4 v = mp[i];
        row[4 * i] = v.x; row[4 * i + 1] = v.y; row[4 * i + 2] = v.z; row[4 * i + 3] = v.w;
    }
    float ipr = 0.f, ipw = 0.f, sq = 0.f, knr = 0.f, knw = 0.f;
#pragma unroll
    for (int m = 0; m < MM; m++) {
        ipr = fmaf(row[m], kr[m], ipr);
        ipw = fmaf(row[m], kw[m], ipw);
        sq  = fmaf(row[m], row[m], sq);
        knr = fmaf(kr[m], kr[m], knr);
        knw = fmaf(kw[m], kw[m], knw);
    }
    knr = sqrtf(knr);
    knw = sqrtf(knw);
    float mn = sqrtf(sq);

    float wread = 0.f, wwrite = 0.f;
#pragma unroll 1
    for (int hd = 0; hd < 2; hd++) {
        const float* hp = rwp + hd * 70;
        float beta  = softplusf(hp[64]);
        float gg    = sigmf(hp[65]);
        float s0r = hp[66], s1r = hp[67], s2r = hp[68];
        float sm = fmaxf(s0r, fmaxf(s1r, s2r));
        float e0 = expf(s0r - sm), e1 = expf(s1r - sm), e2 = expf(s2r - sm);
        float es = e0 + e1 + e2;
        float s0 = e0 / es, s1 = e1 / es, s2 = e2 / es;
        float gamma = softplusf(hp[69]);

        float ip = hd ? ipw : ipr;
        float kn = hd ? knw : knr;
        float Kv = ip / (kn * mn + 1e-8f);

        float e = beta * Kv;
        float emax = blockMax256(e, red);
        float p = expf(e - emax);
        float ps = blockSum256(p, red);
        float wc = p / ps;

        float a = A0[(size_t)hd * BB * NN + (size_t)b * NN + n];
        float wgv = gg * wc + (1.f - gg) * a;
        wgs[n] = wgv;
        __syncthreads();

        float wconv = s0 * wgs[n] + s1 * wgs[(n + NN - 1) & (NN - 1)] + s2 * wgs[(n + 1) & (NN - 1)];
        float wsh = expf(gamma * logf(wconv));
        float wsum = blockSum256(wsh, red);  // ends with syncthreads
        float w = wsh / wsum;

        if (hd == 0) {
            wread = w;
            wrs[n] = w;
            out[OUT_WR + (size_t)b * NN + n] = w;
        } else {
            wwrite = w;
            out[OUT_WW + (size_t)b * NN + n] = w;
        }
        __syncthreads();  // wgs safe to reuse next head
    }

    // m_t = m0 * (1 - ww*del) + ww*add
    float* mt = out + OUT_MT + ((size_t)b * NN + n) * MM;
#pragma unroll
    for (int i = 0; i < MM / 4; i++) {
        float4 v;
        v.x = fmaf(row[4 * i + 0], 1.f - wwrite * dels[4 * i + 0], wwrite * adds[4 * i + 0]);
        v.y = fmaf(row[4 * i + 1], 1.f - wwrite * dels[4 * i + 1], wwrite * adds[4 * i + 1]);
        v.z = fmaf(row[4 * i + 2], 1.f - wwrite * dels[4 * i + 2], wwrite * adds[4 * i + 2]);
        v.w = fmaf(row[4 * i + 3], 1.f - wwrite * dels[4 * i + 3], wwrite * adds[4 * i + 3]);
        ((float4*)mt)[i] = v;
    }

    // R_t[m] = sum_n w_read[n] * m0[b,n,m]  (m0 rereads hit L1/L2)
    __syncthreads();
    if (n < MM) {
        const float* mb = m0 + (size_t)b * NN * MM;
        float acc = 0.f;
        for (int j = 0; j < NN; j++) acc = fmaf(wrs[j], mb[j * MM + n], acc);
        out[OUT_RT + (size_t)b * MM + n] = acc;
        g_Ahr[(size_t)b * HRW + UU + n] = acc;
    }
}

// ---------------- launch ----------------
extern "C" void kernel_launch(void* const* d_in, const int* in_sizes, int n_in,
                              void* d_out, int out_size)
{
    (void)in_sizes; (void)n_in; (void)out_size;
    const float* x_t   = (const float*)d_in[0];
    const float* H0    = (const float*)d_in[1];
    const float* C0    = (const float*)d_in[2];
    const float* m0    = (const float*)d_in[3];
    const float* R0    = (const float*)d_in[4];
    const float* A0    = (const float*)d_in[5];
    const float* Wprep = (const float*)d_in[6];
    const float* bprep = (const float*)d_in[7];
    const float* Wx    = (const float*)d_in[8];
    const float* Wh    = (const float*)d_in[9];
    const float* bl    = (const float*)d_in[10];
    const float* Wr    = (const float*)d_in[11];
    const float* br    = (const float*)d_in[12];
    const float* Ww    = (const float*)d_in[13];
    const float* bw    = (const float*)d_in[14];
    const float* Wo    = (const float*)d_in[15];
    const float* bo    = (const float*)d_in[16];
    float* out = (float*)d_out;

    float *pAbig, *pWbig, *pbbig, *pz, *pAhr, *pWcomb, *pbcomb, *prw;
    cudaGetSymbolAddress((void**)&pAbig,  g_Abig);
    cudaGetSymbolAddress((void**)&pWbig,  g_Wbig);
    cudaGetSymbolAddress((void**)&pbbig,  g_bbig);
    cudaGetSymbolAddress((void**)&pz,     g_z);
    cudaGetSymbolAddress((void**)&pAhr,   g_Ahr);
    cudaGetSymbolAddress((void**)&pWcomb, g_Wcomb);
    cudaGetSymbolAddress((void**)&pbcomb, g_bcomb);
    cudaGetSymbolAddress((void**)&prw,    g_rw);

    // --- prep / packing (independent) ---
    packA_kernel<<<dim3((KBIG + 127) / 128, BB), 128>>>(x_t, R0, H0);
    packWbig_kernel<<<dim3(2048 / 256, KBIG), 256>>>(Wx, Wh);
    bbig_kernel<<<2048 / 256, 256>>>(bl, bprep, Wx);
    packWcomb_kernel<<<UU, RWC>>>(Wr, Ww);
    bcomb_kernel<<<1, RWC>>>(br, bw);
    // Wfused = Wprep @ Wx[10:, :]  into Wbig rows 10..73
    sgemm_kernel<64, 64, 16, 4, 4, false><<<dim3(2048 / 64, 1), 256>>>(
        Wprep, UU, Wx + (size_t)10 * 2048, 2048, nullptr,
        pWbig + (size_t)10 * 2048, 2048, 2048, UU);

    // --- z = Abig @ Wbig + bbig ---
    sgemm_kernel<128, 128, 8, 8, 8, false><<<dim3(2048 / 128, BB / 128), 256>>>(
        pAbig, KBIG, pWbig, 2048, pbbig, pz, 2048, 2048, KBIG);

    // --- LSTM gates -> h (into Ahr cols 0..511) ---
    lstm_kernel<<<(BB * UU) / 256, 256>>>(C0);

    // --- head GEMM: rw = h @ [Wr|Ww] + b ---
    sgemm_kernel<128, 128, 8, 8, 8, false><<<dim3((RWC + 127) / 128, BB / 128), 256>>>(
        pAhr, HRW, pWcomb, RWC, pbcomb, prw, RWC, RWC, UU);

    // --- addressing + memory update + R_t ---
    addr_kernel<<<BB, NN>>>(m0, A0, out);

    // --- y = clip([h|R_t] @ Wo + bo) ---
    sgemm_kernel<128, 128, 8, 8, 8, true><<<dim3(UU / 128, BB / 128), 256>>>(
        pAhr, HRW, Wo, UU, bo, out + OUT_Y, UU, UU, HRW);
}

// round 11
// speedup vs baseline: 1.5191x; 1.5191x over previous
#include <cuda_runtime.h>
#include <cuda_bf16.h>
#include <math.h>
#include <stdint.h>

#define BB   2048
#define NN   256
#define MM   64
#define UU   512
#define INW  10
#define KBIG 592     // 10 + 64 + 512 (+pad)
#define KPADZ 640    // z-GEMM K padded to 64-multiple
#define RWC  272     // 70 + 198 + pad(4)
#define NPADC 384    // rw-GEMM N padded to 128-multiple
#define HRW  576     // 512 + 64  (multiple of 64)
#define CLIPV 20.0f

// ---------------- scratch (static __device__, no allocation) ----------------
__device__ float g_Wbig[(size_t)KBIG * 2048];            // fp32 [Wx[:10]; Wprep@Wx[10:]; Wh; 0]
__device__ float g_bbig[2048];
__device__ float g_z[(size_t)BB * 2048];
__device__ float g_bcomb[RWC];
__device__ float g_rw[(size_t)BB * RWC];

__device__ __nv_bfloat16 g_Az_h[(size_t)BB * KPADZ];     // A for z-GEMM, hi
__device__ __nv_bfloat16 g_Az_l[(size_t)BB * KPADZ];     // lo
__device__ __nv_bfloat16 g_WTz_h[(size_t)2048 * KPADZ];  // Wbig^T [n][k]
__device__ __nv_bfloat16 g_WTz_l[(size_t)2048 * KPADZ];
__device__ __nv_bfloat16 g_Ahr_h[(size_t)BB * HRW];      // [h | R_t]
__device__ __nv_bfloat16 g_Ahr_l[(size_t)BB * HRW];
__device__ __nv_bfloat16 g_WTc_h[(size_t)NPADC * UU];    // [Wr|Ww]^T [n][k]
__device__ __nv_bfloat16 g_WTc_l[(size_t)NPADC * UU];
__device__ __nv_bfloat16 g_WTo_h[(size_t)UU * HRW];      // Wo^T [n][k]
__device__ __nv_bfloat16 g_WTo_l[(size_t)UU * HRW];

// output offsets (floats)
#define OUT_Y  0
#define OUT_MT ((size_t)BB * UU)
#define OUT_RT (OUT_MT + (size_t)BB * NN * MM)
#define OUT_WR (OUT_RT + (size_t)BB * MM)
#define OUT_WW (OUT_WR + (size_t)BB * NN)

// ---------------- small helpers ----------------
__device__ __forceinline__ float sigmf(float x) { return 1.f / (1.f + expf(-x)); }
__device__ __forceinline__ float softplusf(float x) { return x > 20.f ? x : log1pf(expf(x)); }
__device__ __forceinline__ void split_bf(float v, __nv_bfloat16& h, __nv_bfloat16& l) {
    h = __float2bfloat16_rn(v);
    l = __float2bfloat16_rn(v - __bfloat162float(h));
}

// mma.sync m16n8k16 row.col f32.bf16.bf16.f32
__device__ __forceinline__ void mma16816(float* c, const uint32_t* a, uint32_t b0, uint32_t b1) {
    asm volatile(
        "mma.sync.aligned.m16n8k16.row.col.f32.bf16.bf16.f32 "
        "{%0,%1,%2,%3}, {%4,%5,%6,%7}, {%8,%9}, {%0,%1,%2,%3};"
        : "+f"(c[0]), "+f"(c[1]), "+f"(c[2]), "+f"(c[3])
        : "r"(a[0]), "r"(a[1]), "r"(a[2]), "r"(a[3]), "r"(b0), "r"(b1));
}

// ============ warp-MMA GEMM: C[m][n] = sum_k (Ah+Al)[m][k]*(Bh+Bl)[n][k] + bias ============
// A: bf16 hi/lo [Mrows][lda] K-major.  B: bf16 hi/lo [Nrows][ldb] K-major (= W^T).
// Block tile 128x128, K-tile 32; 8 warps: warp_m = wid&3 (32 rows), warp_n = wid>>2 (64 cols).
// Requires: Mrows % 128 == 0, B has >= gridDim.x*128 rows, K % 32 == 0, lda/ldb % 8 == 0.
#define SPAD 40
template <bool DOCLIP>
__global__ void __launch_bounds__(256, 1) wmma_gemm(
    const __nv_bfloat16* __restrict__ Ah, const __nv_bfloat16* __restrict__ Al, int lda,
    const __nv_bfloat16* __restrict__ Bh, const __nv_bfloat16* __restrict__ Bl, int ldb,
    const float* __restrict__ bias,
    float* __restrict__ C, int ldc, int Ncols, int K)
{
    __shared__ __nv_bfloat16 sA[2][128][SPAD];   // [hi/lo][m][k]
    __shared__ __nv_bfloat16 sB[2][128][SPAD];   // [hi/lo][n][k]

    const int tid  = threadIdx.x;
    const int wid  = tid >> 5;
    const int lane = tid & 31;
    const int g    = lane >> 2;     // group id (0..7)
    const int tig  = lane & 3;      // thread in group
    const int warp_m = wid & 3;     // 0..3  -> 32-row slice
    const int warp_n = wid >> 2;    // 0..1  -> 64-col slice
    const int m0 = blockIdx.y * 128;
    const int n0 = blockIdx.x * 128;

    float acc[2][8][4];
#pragma unroll
    for (int mf = 0; mf < 2; mf++)
#pragma unroll
        for (int nf = 0; nf < 8; nf++)
#pragma unroll
            for (int i = 0; i < 4; i++) acc[mf][nf][i] = 0.f;

    const int lrow = tid >> 2;          // 0..63 (x2 iters -> 128 rows)
    const int lkc  = (tid & 3) * 8;     // bf16 element offset within 32-wide K tile

    const int ktiles = K >> 5;
    for (int kt = 0; kt < ktiles; kt++) {
        const int kbase = kt * 32 + lkc;
#pragma unroll
        for (int i = 0; i < 2; i++) {
            int row = lrow + 64 * i;
            *(uint4*)&sA[0][row][lkc] = *(const uint4*)&Ah[(size_t)(m0 + row) * lda + kbase];
            *(uint4*)&sA[1][row][lkc] = *(const uint4*)&Al[(size_t)(m0 + row) * lda + kbase];
            *(uint4*)&sB[0][row][lkc] = *(const uint4*)&Bh[(size_t)(n0 + row) * ldb + kbase];
            *(uint4*)&sB[1][row][lkc] = *(const uint4*)&Bl[(size_t)(n0 + row) * ldb + kbase];
        }
        __syncthreads();

#pragma unroll
        for (int ks = 0; ks < 32; ks += 16) {
            // A fragments (hi and lo) for both 16-row sub-tiles
            uint32_t ah[2][4], al[2][4];
#pragma unroll
            for (int mf = 0; mf < 2; mf++) {
                const __nv_bfloat16* pa = &sA[0][warp_m * 32 + mf * 16 + g][ks + 2 * tig];
                const __nv_bfloat16* pl = &sA[1][warp_m * 32 + mf * 16 + g][ks + 2 * tig];
                ah[mf][0] = *(const uint32_t*)pa;
                ah[mf][1] = *(const uint32_t*)(pa + 8 * SPAD);
                ah[mf][2] = *(const uint32_t*)(pa + 8);
                ah[mf][3] = *(const uint32_t*)(pa + 8 * SPAD + 8);
                al[mf][0] = *(const uint32_t*)pl;
                al[mf][1] = *(const uint32_t*)(pl + 8 * SPAD);
                al[mf][2] = *(const uint32_t*)(pl + 8);
                al[mf][3] = *(const uint32_t*)(pl + 8 * SPAD + 8);
            }
#pragma unroll
            for (int nf = 0; nf < 8; nf++) {
                const __nv_bfloat16* pb = &sB[0][warp_n * 64 + nf * 8 + g][ks + 2 * tig];
                const __nv_bfloat16* pq = &sB[1][warp_n * 64 + nf * 8 + g][ks + 2 * tig];
                uint32_t bh0 = *(const uint32_t*)pb;
                uint32_t bh1 = *(const uint32_t*)(pb + 8);
                uint32_t bl0 = *(const uint32_t*)pq;
                uint32_t bl1 = *(const uint32_t*)(pq + 8);
#pragma unroll
                for (int mf = 0; mf < 2; mf++) {
                    mma16816(acc[mf][nf], ah[mf], bh0, bh1);   // hi*hi
                    mma16816(acc[mf][nf], ah[mf], bl0, bl1);   // hi*lo
                    mma16816(acc[mf][nf], al[mf], bh0, bh1);   // lo*hi
                }
            }
        }
        __syncthreads();
    }

    // epilogue: fragment-direct stores
#pragma unroll
    for (int mf = 0; mf < 2; mf++) {
        int row = m0 + warp_m * 32 + mf * 16 + g;
#pragma unroll
        for (int nf = 0; nf < 8; nf++) {
            int col = n0 + warp_n * 64 + nf * 8 + 2 * tig;
            if (col < Ncols) {
                float b0 = bias ? bias[col] : 0.f;
                float v0 = acc[mf][nf][0] + b0;
                float v2 = acc[mf][nf][2] + b0;
                if (DOCLIP) {
                    v0 = fminf(CLIPV, fmaxf(-CLIPV, v0));
                    v2 = fminf(CLIPV, fmaxf(-CLIPV, v2));
                }
                C[(size_t)row * ldc + col] = v0;
                C[(size_t)(row + 8) * ldc + col] = v2;
            }
            if (col + 1 < Ncols) {
                float b1 = bias ? bias[col + 1] : 0.f;
                float v1 = acc[mf][nf][1] + b1;
                float v3 = acc[mf][nf][3] + b1;
                if (DOCLIP) {
                    v1 = fminf(CLIPV, fmaxf(-CLIPV, v1));
                    v3 = fminf(CLIPV, fmaxf(-CLIPV, v3));
                }
                C[(size_t)row * ldc + col + 1] = v1;
                C[(size_t)(row + 8) * ldc + col + 1] = v3;
            }
        }
    }
}

// ---------------- fp32 SIMT GEMM (small Wfused only) ----------------
template <int MT, int NT, int KT, int TM, int TN>
__global__ void __launch_bounds__(256) sgemm_kernel(
    const float* __restrict__ A, int lda,
    const float* __restrict__ B, int ldb,
    float* __restrict__ C, int ldc,
    int Ncols, int K)
{
    const int tid = threadIdx.x;
    const int tx = tid % (NT / TN);
    const int ty = tid / (NT / TN);
    const int m0 = blockIdx.y * MT;
    const int n0 = blockIdx.x * NT;
    __shared__ float As[KT][MT];
    __shared__ float Bs[KT][NT];
    float acc[TM][TN];
#pragma unroll
    for (int i = 0; i < TM; i++)
#pragma unroll
        for (int j = 0; j < TN; j++) acc[i][j] = 0.f;
    const int arow = tid / (KT / 4);
    const int ac   = (tid % (KT / 4)) * 4;
    const int brow = tid / (NT / 4);
    const int bc   = (tid % (NT / 4)) * 4;
    for (int k0 = 0; k0 < K; k0 += KT) {
        {
            float4 v = *(const float4*)&A[(size_t)(m0 + arow) * lda + k0 + ac];
            As[ac + 0][arow] = v.x; As[ac + 1][arow] = v.y;
            As[ac + 2][arow] = v.z; As[ac + 3][arow] = v.w;
        }
        {
            int gc = n0 + bc;
            float4 v = make_float4(0.f, 0.f, 0.f, 0.f);
            if (gc < Ncols) v = *(const float4*)&B[(size_t)(k0 + brow) * ldb + gc];
            *(float4*)&Bs[brow][bc] = v;
        }
        __syncthreads();
#pragma unroll
        for (int k = 0; k < KT; k++) {
            float a[TM], b[TN];
#pragma unroll
            for (int i = 0; i < TM; i++) a[i] = As[k][ty * TM + i];
#pragma unroll
            for (int j = 0; j < TN; j++) b[j] = Bs[k][tx * TN + j];
#pragma unroll
            for (int i = 0; i < TM; i++)
#pragma unroll
                for (int j = 0; j < TN; j++) acc[i][j] = fmaf(a[i], b[j], acc[i][j]);
        }
        __syncthreads();
    }
#pragma unroll
    for (int i = 0; i < TM; i++) {
        int r = m0 + ty * TM + i;
#pragma unroll
        for (int j = 0; j < TN; j++) {
            int c = n0 + tx * TN + j;
            if (c < Ncols) C[(size_t)r * ldc + c] = acc[i][j];
        }
    }
}

// ---------------- pack / transpose kernels ----------------
__global__ void packWbig_kernel(const float* __restrict__ Wx, const float* __restrict__ Wh)
{
    int c = blockIdx.x * 256 + threadIdx.x;
    int r = blockIdx.y;
    if (r >= 10 && r < 74) return;  // filled by fuse GEMM
    float v = 0.f;
    if (r < 10)       v = Wx[(size_t)r * 2048 + c];
    else if (r < 586) v = Wh[(size_t)(r - 74) * 2048 + c];
    g_Wbig[(size_t)r * 2048 + c] = v;
}

__global__ void bbig_kernel(const float* __restrict__ bl, const float* __restrict__ bprep,
                            const float* __restrict__ Wx)
{
    int c = blockIdx.x * 256 + threadIdx.x;
    float acc = bl[c];
    for (int u = 0; u < UU; u++)
        acc = fmaf(bprep[u], Wx[(size_t)(10 + u) * 2048 + c], acc);
    g_bbig[c] = acc;
}

// Wbig [592][2048] fp32 -> WTz hi/lo [2048][640] bf16 (tiled transpose+split)
__global__ void transWz_kernel()
{
    __shared__ float t[32][33];
    int n0 = blockIdx.x * 32, k0 = blockIdx.y * 32;
    int tx = threadIdx.x, ty = threadIdx.y;
    for (int j = ty; j < 32; j += 8) {
        int k = k0 + j;
        t[j][tx] = (k < KBIG) ? g_Wbig[(size_t)k * 2048 + n0 + tx] : 0.f;
    }
    __syncthreads();
    for (int j = ty; j < 32; j += 8) {
        int n = n0 + j, k = k0 + tx;
        __nv_bfloat16 h, l;
        split_bf(t[tx][j], h, l);
        g_WTz_h[(size_t)n * KPADZ + k] = h;
        g_WTz_l[(size_t)n * KPADZ + k] = l;
    }
}

// A for z-GEMM: [x | R0 | H0 | 0] -> bf16 hi/lo [2048][640]
__global__ void packAbf_kernel(const float* __restrict__ x, const float* __restrict__ R0,
                               const float* __restrict__ H0)
{
    int c = blockIdx.x * 128 + threadIdx.x;
    int b = blockIdx.y;
    if (c >= KPADZ) return;
    float v = 0.f;
    if (c < INW)                 v = x[b * INW + c];
    else if (c < INW + MM)       v = R0[b * MM + (c - INW)];
    else if (c < INW + MM + UU)  v = H0[b * UU + (c - (INW + MM))];
    __nv_bfloat16 h, l;
    split_bf(v, h, l);
    g_Az_h[(size_t)b * KPADZ + c] = h;
    g_Az_l[(size_t)b * KPADZ + c] = l;
}

// [Wr|Ww]^T -> WTc hi/lo [384][512]
__global__ void gatherWTc_kernel(const float* __restrict__ Wr, const float* __restrict__ Ww)
{
    int k = blockIdx.x * 128 + threadIdx.x;   // 512
    int n = blockIdx.y;                       // 384
    float v = 0.f;
    if (n < 70)        v = Wr[(size_t)k * 70 + n];
    else if (n < 268)  v = Ww[(size_t)k * 198 + (n - 70)];
    __nv_bfloat16 h, l;
    split_bf(v, h, l);
    g_WTc_h[(size_t)n * UU + k] = h;
    g_WTc_l[(size_t)n * UU + k] = l;
}

// Wo^T -> WTo hi/lo [512][576]
__global__ void gatherWTo_kernel(const float* __restrict__ Wo)
{
    int k = blockIdx.x * 128 + threadIdx.x;   // up to 576
    int n = blockIdx.y;                       // 512
    if (k >= HRW) return;
    __nv_bfloat16 h, l;
    split_bf(Wo[(size_t)k * UU + n], h, l);
    g_WTo_h[(size_t)n * HRW + k] = h;
    g_WTo_l[(size_t)n * HRW + k] = l;
}

__global__ void bcomb_kernel(const float* __restrict__ br, const float* __restrict__ bw)
{
    int c = threadIdx.x;
    float v = 0.f;
    if (c < 70)       v = br[c];
    else if (c < 268) v = bw[c - 70];
    g_bcomb[c] = v;
}

// ---------------- LSTM elementwise -> h (bf16 split into Ahr) ----------------
__global__ void lstm_kernel(const float* __restrict__ C0)
{
    int t = blockIdx.x * blockDim.x + threadIdx.x;
    if (t >= BB * UU) return;
    int b = t >> 9;
    int u = t & 511;
    const float* zr = g_z + (size_t)b * 2048;
    float iv = zr[u], fv = zr[512 + u], gv = zr[1024 + u], ov = zr[1536 + u];
    float ct = sigmf(fv) * C0[t] + sigmf(iv) * tanhf(gv);
    float h = sigmf(ov) * tanhf(ct);
    h = fminf(CLIPV, fmaxf(-CLIPV, h));
    __nv_bfloat16 hh, hl;
    split_bf(h, hh, hl);
    g_Ahr_h[(size_t)b * HRW + u] = hh;
    g_Ahr_l[(size_t)b * HRW + u] = hl;
}

// ---------------- reductions ----------------
__device__ __forceinline__ float blockSum256(float v, float* red) {
#pragma unroll
    for (int o = 16; o; o >>= 1) v += __shfl_xor_sync(0xffffffffu, v, o);
    if ((threadIdx.x & 31) == 0) red[threadIdx.x >> 5] = v;
    __syncthreads();
    float t = 0.f;
#pragma unroll
    for (int i = 0; i < 8; i++) t += red[i];
    __syncthreads();
    return t;
}
__device__ __forceinline__ float blockMax256(float v, float* red) {
#pragma unroll
    for (int o = 16; o; o >>= 1) v = fmaxf(v, __shfl_xor_sync(0xffffffffu, v, o));
    if ((threadIdx.x & 31) == 0) red[threadIdx.x >> 5] = v;
    __syncthreads();
    float t = -1e30f;
#pragma unroll
    for (int i = 0; i < 8; i++) t = fmaxf(t, red[i]);
    __syncthreads();
    return t;
}

// ---------------- fused addressing + memory update ----------------
__global__ void __launch_bounds__(256) addr_kernel(
    const float* __restrict__ m0,
    const float* __restrict__ A0,
    float* __restrict__ out)
{
    const int b = blockIdx.x;
    const int n = threadIdx.x;
    const float* rwp = g_rw + (size_t)b * RWC;

    __shared__ float kr[MM], kw[MM], dels[MM], adds[MM];
    __shared__ float wgs[NN], wrs[NN];
    __shared__ float red[8];

    if (n < MM) {
        kr[n]   = tanhf(rwp[n]);
        kw[n]   = tanhf(rwp[70 + n]);
        dels[n] = sigmf(rwp[140 + n]);
        adds[n] = tanhf(rwp[204 + n]);
    }
    __syncthreads();

    float row[MM];
    const float4* mp = (const float4*)(m0 + ((size_t)b * NN + n) * MM);
#pragma unroll
    for (int i = 0; i < MM / 4; i++) {
        float4 v = mp[i];
        row[4 * i] = v.x; row[4 * i + 1] = v.y; row[4 * i + 2] = v.z; row[4 * i + 3] = v.w;
    }
    float ipr = 0.f, ipw = 0.f, sq = 0.f, knr = 0.f, knw = 0.f;
#pragma unroll
    for (int m = 0; m < MM; m++) {
        ipr = fmaf(row[m], kr[m], ipr);
        ipw = fmaf(row[m], kw[m], ipw);
        sq  = fmaf(row[m], row[m], sq);
        knr = fmaf(kr[m], kr[m], knr);
        knw = fmaf(kw[m], kw[m], knw);
    }
    knr = sqrtf(knr);
    knw = sqrtf(knw);
    float mn = sqrtf(sq);

    float wwrite = 0.f;
#pragma unroll 1
    for (int hd = 0; hd < 2; hd++) {
        const float* hp = rwp + hd * 70;
        float beta  = softplusf(hp[64]);
        float gg    = sigmf(hp[65]);
        float s0r = hp[66], s1r = hp[67], s2r = hp[68];
        float sm = fmaxf(s0r, fmaxf(s1r, s2r));
        float e0 = expf(s0r - sm), e1 = expf(s1r - sm), e2 = expf(s2r - sm);
        float es = e0 + e1 + e2;
        float s0 = e0 / es, s1 = e1 / es, s2 = e2 / es;
        float gamma = softplusf(hp[69]);

        float ip = hd ? ipw : ipr;
        float kn = hd ? knw : knr;
        float Kv = ip / (kn * mn + 1e-8f);

        float e = beta * Kv;
        float emax = blockMax256(e, red);
        float p = expf(e - emax);
        float ps = blockSum256(p, red);
        float wc = p / ps;

        float a = A0[(size_t)hd * BB * NN + (size_t)b * NN + n];
        float wgv = gg * wc + (1.f - gg) * a;
        wgs[n] = wgv;
        __syncthreads();

        float wconv = s0 * wgs[n] + s1 * wgs[(n + NN - 1) & (NN - 1)] + s2 * wgs[(n + 1) & (NN - 1)];
        float wsh = expf(gamma * logf(wconv));
        float wsum = blockSum256(wsh, red);
        float w = wsh / wsum;

        if (hd == 0) {
            wrs[n] = w;
            out[OUT_WR + (size_t)b * NN + n] = w;
        } else {
            wwrite = w;
            out[OUT_WW + (size_t)b * NN + n] = w;
        }
        __syncthreads();
    }

    float* mt = out + OUT_MT + ((size_t)b * NN + n) * MM;
#pragma unroll
    for (int i = 0; i < MM / 4; i++) {
        float4 v;
        v.x = fmaf(row[4 * i + 0], 1.f - wwrite * dels[4 * i + 0], wwrite * adds[4 * i + 0]);
        v.y = fmaf(row[4 * i + 1], 1.f - wwrite * dels[4 * i + 1], wwrite * adds[4 * i + 1]);
        v.z = fmaf(row[4 * i + 2], 1.f - wwrite * dels[4 * i + 2], wwrite * adds[4 * i + 2]);
        v.w = fmaf(row[4 * i + 3], 1.f - wwrite * dels[4 * i + 3], wwrite * adds[4 * i + 3]);
        ((float4*)mt)[i] = v;
    }

    __syncthreads();
    if (n < MM) {
        const float* mb = m0 + (size_t)b * NN * MM;
        float acc = 0.f;
        for (int j = 0; j < NN; j++) acc = fmaf(wrs[j], mb[j * MM + n], acc);
        out[OUT_RT + (size_t)b * MM + n] = acc;
        __nv_bfloat16 h, l;
        split_bf(acc, h, l);
        g_Ahr_h[(size_t)b * HRW + UU + n] = h;
        g_Ahr_l[(size_t)b * HRW + UU + n] = l;
    }
}

// ---------------- launch ----------------
extern "C" void kernel_launch(void* const* d_in, const int* in_sizes, int n_in,
                              void* d_out, int out_size)
{
    (void)in_sizes; (void)n_in; (void)out_size;
    const float* x_t   = (const float*)d_in[0];
    const float* H0    = (const float*)d_in[1];
    const float* C0    = (const float*)d_in[2];
    const float* m0    = (const float*)d_in[3];
    const float* R0    = (const float*)d_in[4];
    const float* A0    = (const float*)d_in[5];
    const float* Wprep = (const float*)d_in[6];
    const float* bprep = (const float*)d_in[7];
    const float* Wx    = (const float*)d_in[8];
    const float* Wh    = (const float*)d_in[9];
    const float* bl    = (const float*)d_in[10];
    const float* Wr    = (const float*)d_in[11];
    const float* br    = (const float*)d_in[12];
    const float* Ww    = (const float*)d_in[13];
    const float* bw    = (const float*)d_in[14];
    const float* Wo    = (const float*)d_in[15];
    const float* bo    = (const float*)d_in[16];
    float* out = (float*)d_out;

    float *pWbig, *pbbig, *pz, *pbcomb, *prw;
    __nv_bfloat16 *pAzh, *pAzl, *pWTzh, *pWTzl, *pAhrh, *pAhrl, *pWTch, *pWTcl, *pWToh, *pWTol;
    cudaGetSymbolAddress((void**)&pWbig,  g_Wbig);
    cudaGetSymbolAddress((void**)&pbbig,  g_bbig);
    cudaGetSymbolAddress((void**)&pz,     g_z);
    cudaGetSymbolAddress((void**)&pbcomb, g_bcomb);
    cudaGetSymbolAddress((void**)&prw,    g_rw);
    cudaGetSymbolAddress((void**)&pAzh,   g_Az_h);
    cudaGetSymbolAddress((void**)&pAzl,   g_Az_l);
    cudaGetSymbolAddress((void**)&pWTzh,  g_WTz_h);
    cudaGetSymbolAddress((void**)&pWTzl,  g_WTz_l);
    cudaGetSymbolAddress((void**)&pAhrh,  g_Ahr_h);
    cudaGetSymbolAddress((void**)&pAhrl,  g_Ahr_l);
    cudaGetSymbolAddress((void**)&pWTch,  g_WTc_h);
    cudaGetSymbolAddress((void**)&pWTcl,  g_WTc_l);
    cudaGetSymbolAddress((void**)&pWToh,  g_WTo_h);
    cudaGetSymbolAddress((void**)&pWTol,  g_WTo_l);

    // 1. Wbig rows (except fused block)
    packWbig_kernel<<<dim3(2048 / 256, KBIG), 256>>>(Wx, Wh);
    // 2. Wfused = Wprep @ Wx[10:, :] into Wbig rows 10..73
    sgemm_kernel<64, 64, 16, 4, 4><<<dim3(2048 / 64, 1), 256>>>(
        Wprep, UU, Wx + (size_t)10 * 2048, 2048,
        pWbig + (size_t)10 * 2048, 2048, 2048, UU);
    // 3. fused bias
    bbig_kernel<<<2048 / 256, 256>>>(bl, bprep, Wx);
    // 4. transpose+split Wbig -> WTz
    transWz_kernel<<<dim3(2048 / 32, KPADZ / 32), dim3(32, 8)>>>();
    // 5. pack A (bf16 split)
    packAbf_kernel<<<dim3((KPADZ + 127) / 128, BB), 128>>>(x_t, R0, H0);
    // 6. z = A @ Wbig + bbig   (warp MMA)  <-- ncu -s 5 capture target
    wmma_gemm<false><<<dim3(2048 / 128, BB / 128), 256>>>(
        pAzh, pAzl, KPADZ, pWTzh, pWTzl, KPADZ, pbbig, pz, 2048, 2048, KPADZ);
    // 7. LSTM -> h
    lstm_kernel<<<(BB * UU) / 256, 256>>>(C0);
    // 8. [Wr|Ww]^T
    gatherWTc_kernel<<<dim3(UU / 128, NPADC), 128>>>(Wr, Ww);
    // 9. head bias
    bcomb_kernel<<<1, RWC>>>(br, bw);
    // 10. rw = h @ [Wr|Ww] + bcomb   (K=512, first 512 cols of Ahr)
    wmma_gemm<false><<<dim3(NPADC / 128, BB / 128), 256>>>(
        pAhrh, pAhrl, HRW, pWTch, pWTcl, UU, pbcomb, prw, RWC, RWC, UU);
    // 11. addressing + memory update + R_t
    addr_kernel<<<BB, NN>>>(m0, A0, out);
    // 12. Wo^T
    gatherWTo_kernel<<<dim3((HRW + 127) / 128, UU), 128>>>(Wo);
    // 13. y = clip([h|R_t] @ Wo + bo)
    wmma_gemm<true><<<dim3(UU / 128, BB / 128), 256>>>(
        pAhrh, pAhrl, HRW, pWToh, pWTol, HRW, bo, out + OUT_Y, UU, UU, HRW);
}